// round 14
// baseline (speedup 1.0000x reference)
#include <cuda_runtime.h>
#include <math.h>

#define NB 128      // batch
#define NS 512      // sequence length
#define NH 1024     // hidden dim
#define NE 128      // label embedding dim
#define NL 32       // num labels
#define G3 3072     // 3*NH
#define KH 1152     // NH + NE
#define NCTA 128    // persistent CTAs (<= 148 SMs, all co-resident)

// ---------------- device scratch (static globals: allocation-free) ----------------
__device__ float g_xT[(size_t)NS * NH * NB];     // [s][k][b]
__device__ float g_gix[(size_t)NS * G3 * NB];    // [s][row][b] x-part of gi + b_ih
__device__ float g_hT[2][NH * NB];               // h state, [k][b], double buffered
__device__ float g_labT[2][NE * NB];             // label embedding, [e][b], double buffered
__device__ float g_woutT[NH * NL];               // [k][l]
__device__ unsigned g_bar_cnt;
__device__ unsigned g_bar_gen;

typedef unsigned long long u64;

// ---------------- f32x2 helpers ----------------
__device__ __forceinline__ u64 pk2(float v) {
    u64 r; unsigned u = __float_as_uint(v);
    asm("mov.b64 %0, {%1, %2};" : "=l"(r) : "r"(u), "r"(u));
    return r;
}
__device__ __forceinline__ void fma2(u64 &d, u64 a, u64 b) {
    asm("fma.rn.f32x2 %0, %1, %2, %0;" : "+l"(d) : "l"(a), "l"(b));
}
__device__ __forceinline__ float2 upk(u64 v) {
    unsigned lo, hi;
    asm("mov.b64 {%0, %1}, %2;" : "=r"(lo), "=r"(hi) : "l"(v));
    return make_float2(__uint_as_float(lo), __uint_as_float(hi));
}

__device__ __forceinline__ float sigm(float x) { return 1.0f / (1.0f + expf(-x)); }
__device__ __forceinline__ float tanh_s(float x) {
    float ax = fabsf(x);
    float e  = expf(-2.0f * ax);
    float t  = (1.0f - e) / (1.0f + e);
    return (x < 0.0f) ? -t : t;
}

// ---------------- global barrier (all NCTA CTAs co-resident) ----------------
__device__ __forceinline__ void gbar(unsigned epoch) {
    __syncthreads();
    if (threadIdx.x == 0) {
        __threadfence();
        unsigned a = atomicAdd(&g_bar_cnt, 1u) + 1u;
        if (a == (unsigned)NCTA * epoch) {
            atomicExch(&g_bar_gen, epoch);
        } else {
            volatile unsigned* gen = &g_bar_gen;
            while (*gen < epoch) { __nanosleep(64); }
        }
        __threadfence();
    }
    __syncthreads();
}

// ---------------- kernel: transpose x[b][s][k] -> xT[s][k][b] ----------------
__global__ __launch_bounds__(256) void k_transpose(const float* __restrict__ x) {
    int s  = blockIdx.x;
    int k0 = blockIdx.y * 64;
    __shared__ float t[64][NB + 1];
    for (int i = threadIdx.x; i < 64 * NB; i += 256) {
        int b = i >> 6, kk = i & 63;
        t[kk][b] = x[((size_t)b * NS + s) * NH + k0 + kk];
    }
    __syncthreads();
    for (int i = threadIdx.x; i < 64 * NB; i += 256) {
        int kk = i >> 7, b = i & 127;
        g_xT[((size_t)s * NH + k0 + kk) * NB + b] = t[kk][b];
    }
}

// ---------------- kernel: init ----------------
__global__ void k_init(const float* __restrict__ emb, const float* __restrict__ Wout) {
    int tid = blockIdx.x * blockDim.x + threadIdx.x;
    int nt  = gridDim.x * blockDim.x;
    for (int i = tid; i < NH * NB; i += nt) g_hT[0][i] = 0.0f;
    for (int i = tid; i < NE * NB; i += nt) {
        int e = i >> 7, b = i & 127;
        g_labT[0][e * NB + b] = emb[e];          // emb[label id 0]
    }
    for (int i = tid; i < NH * NL; i += nt) {
        int k = i >> 5, l = i & 31;
        g_woutT[i] = Wout[(size_t)l * NH + k];
    }
    if (tid == 0) { g_bar_cnt = 0u; g_bar_gen = 0u; }
}

// ---------------- kernel: phase A  gix[s][row][b] = W_ih[:, :1024] . x + b_ih ----------------
__global__ __launch_bounds__(256) void k_gemm_a(const float* __restrict__ Wih,
                                                const float* __restrict__ bih) {
    __shared__ u64 w2[48 * 128];   // 48 KB, weights duplicated into (w,w) pairs
    int s       = blockIdx.y;
    int rowbase = blockIdx.x * 48;
    int t  = threadIdx.x;
    int bp = t & 63, tr = t >> 6;

    u64 acc[12];
    #pragma unroll
    for (int i = 0; i < 12; i++) acc[i] = 0ull;

    const float* xs = g_xT + (size_t)s * NH * NB;

    for (int kt = 0; kt < 8; kt++) {
        int k0 = kt << 7;
        __syncthreads();
        for (int i = t; i < 48 * 32; i += 256) {
            int lr = i >> 5, kq = (i & 31) << 2;
            float4 v = *(const float4*)&Wih[(size_t)(rowbase + lr) * KH + k0 + kq];
            u64* dst = &w2[lr * 128 + kq];
            dst[0] = pk2(v.x); dst[1] = pk2(v.y); dst[2] = pk2(v.z); dst[3] = pk2(v.w);
        }
        __syncthreads();
        const u64* wb = &w2[(tr * 12) * 128];
        for (int kk = 0; kk < 128; kk += 2) {
            u64 x0 = *(const u64*)&xs[(size_t)(k0 + kk) * NB + 2 * bp];
            u64 x1 = *(const u64*)&xs[(size_t)(k0 + kk + 1) * NB + 2 * bp];
            #pragma unroll
            for (int rr = 0; rr < 12; rr++) {
                fma2(acc[rr], wb[rr * 128 + kk],     x0);
                fma2(acc[rr], wb[rr * 128 + kk + 1], x1);
            }
        }
    }

    float* go = g_gix + ((size_t)s * G3 + rowbase) * NB;
    #pragma unroll
    for (int rr = 0; rr < 12; rr++) {
        int lr = tr * 12 + rr;
        float2 v = upk(acc[rr]);
        float bias = bih[rowbase + lr];
        v.x += bias; v.y += bias;
        *(float2*)&go[(size_t)lr * NB + 2 * bp] = v;
    }
}

// ---------------- persistent sequential kernel ----------------
// smem layout (bytes):
//   [0,       98304)  wpair : u64[12][1024]  W_hh slice, row-pair interleaved
//   [98304,  110592)  lwpair: u64[12][128]   W_ih label-part slice, row-pair interleaved
//   [110592, 144384)  union: red2 float2[128][16] (GRU half-exchange)
//                            sred float[256][33]  (logits reduce)
//   [144384, ...)     sb[24] bhh slice, sbo[32] bout, stot[32], spred
#define SMEM_SEQ 145408

__global__ __launch_bounds__(256) void k_seq(
    const float* __restrict__ Whh, const float* __restrict__ Wih,
    const float* __restrict__ bhh, const float* __restrict__ emb,
    const float* __restrict__ bout, float* __restrict__ out)
{
    extern __shared__ char sm[];
    u64*    wpair  = (u64*)sm;
    u64*    lwpair = (u64*)(sm + 98304);
    float2* red2   = (float2*)(sm + 110592);
    float*  sred   = (float*)(sm + 110592);
    float*  sb     = (float*)(sm + 144384);
    float*  sbo    = sb + 24;
    float*  stot   = sbo + 32;
    int*    spred  = (int*)(stot + 32);

    const int c = blockIdx.x;
    const int t = threadIdx.x;
    const int b = t & 127;
    const int half = t >> 7;

    // ---- one-time preload: W_hh slice (24 rows) as row-pair interleaved u32 ----
    unsigned* wp32 = (unsigned*)wpair;
    for (int idx = t; idx < 24 * 256; idx += 256) {
        int row = idx >> 8;            // 0..23  (g = row/8, jl = row%8)
        int kq  = (idx & 255) << 2;    // 0..1020 step 4
        int g = row >> 3, jl = row & 7;
        int p = g * 4 + (jl >> 1), lane = jl & 1;
        float4 v = *(const float4*)&Whh[(size_t)(g * NH + c * 8 + jl) * NH + kq];
        wp32[((p * 1024 + kq + 0) << 1) + lane] = __float_as_uint(v.x);
        wp32[((p * 1024 + kq + 1) << 1) + lane] = __float_as_uint(v.y);
        wp32[((p * 1024 + kq + 2) << 1) + lane] = __float_as_uint(v.z);
        wp32[((p * 1024 + kq + 3) << 1) + lane] = __float_as_uint(v.w);
    }
    unsigned* lp32 = (unsigned*)lwpair;
    for (int idx = t; idx < 24 * 32; idx += 256) {
        int row = idx >> 5;
        int kq  = (idx & 31) << 2;
        int g = row >> 3, jl = row & 7;
        int p = g * 4 + (jl >> 1), lane = jl & 1;
        float4 v = *(const float4*)&Wih[(size_t)(g * NH + c * 8 + jl) * KH + NH + kq];
        lp32[((p * 128 + kq + 0) << 1) + lane] = __float_as_uint(v.x);
        lp32[((p * 128 + kq + 1) << 1) + lane] = __float_as_uint(v.y);
        lp32[((p * 128 + kq + 2) << 1) + lane] = __float_as_uint(v.z);
        lp32[((p * 128 + kq + 3) << 1) + lane] = __float_as_uint(v.w);
    }
    if (t < 24) sb[t]  = bhh[(t >> 3) * NH + c * 8 + (t & 7)];
    if (t < 32) sbo[t] = bout[t];
    __syncthreads();

    unsigned epoch = 0;
    for (int s = 0; s < NS; s++) {
        const float* hin  = g_hT[s & 1];
        const float* lin  = g_labT[s & 1];
        float*       hout = g_hT[(s + 1) & 1];
        float*       lout = g_labT[(s + 1) & 1];

        // ======== GRU phase: gh = h @ Whh.T (split over k-halves) ========
        u64 acc[12], accLn[4];
        #pragma unroll
        for (int p = 0; p < 12; p++) acc[p] = 0ull;
        #pragma unroll
        for (int p = 0; p < 4; p++)  accLn[p] = 0ull;

        const int kb = half << 9;
        for (int k = kb; k < kb + 512; k += 2) {
            u64 hp0 = pk2(hin[k * NB + b]);
            u64 hp1 = pk2(hin[(k + 1) * NB + b]);
            #pragma unroll
            for (int p = 0; p < 12; p++) {
                ulonglong2 w = *(const ulonglong2*)&wpair[p * 1024 + k];
                fma2(acc[p], w.x, hp0);
                fma2(acc[p], w.y, hp1);
            }
        }
        // label-embedding part: K = 128; r,z fold into acc; n stays separate
        const int lb = half << 6;
        for (int k = lb; k < lb + 64; k += 2) {
            u64 lp0 = pk2(lin[k * NB + b]);
            u64 lp1 = pk2(lin[(k + 1) * NB + b]);
            #pragma unroll
            for (int p = 0; p < 8; p++) {
                ulonglong2 w = *(const ulonglong2*)&lwpair[p * 128 + k];
                fma2(acc[p], w.x, lp0);
                fma2(acc[p], w.y, lp1);
            }
            #pragma unroll
            for (int p = 0; p < 4; p++) {
                ulonglong2 w = *(const ulonglong2*)&lwpair[(8 + p) * 128 + k];
                fma2(accLn[p], w.x, lp0);
                fma2(accLn[p], w.y, lp1);
            }
        }

        // half-exchange then gate math (half 0 threads)
        if (half) {
            #pragma unroll
            for (int p = 0; p < 12; p++) red2[b * 16 + p] = upk(acc[p]);
            #pragma unroll
            for (int p = 0; p < 4; p++)  red2[b * 16 + 12 + p] = upk(accLn[p]);
        }
        __syncthreads();
        if (!half) {
            const float* gix = g_gix + (size_t)s * G3 * NB;
            #pragma unroll
            for (int pp = 0; pp < 4; pp++) {
                float2 gr = upk(acc[pp]);       { float2 o = red2[b*16 + pp];      gr.x += o.x; gr.y += o.y; }
                float2 gz = upk(acc[4 + pp]);   { float2 o = red2[b*16 + 4 + pp];  gz.x += o.x; gz.y += o.y; }
                float2 gn = upk(acc[8 + pp]);   { float2 o = red2[b*16 + 8 + pp];  gn.x += o.x; gn.y += o.y; }
                float2 ln = upk(accLn[pp]);     { float2 o = red2[b*16 + 12 + pp]; ln.x += o.x; ln.y += o.y; }
                #pragma unroll
                for (int e = 0; e < 2; e++) {
                    int jl = 2 * pp + e;
                    int j  = c * 8 + jl;
                    float ghr = e ? gr.y : gr.x;
                    float ghz = e ? gz.y : gz.x;
                    float ghn = e ? gn.y : gn.x;
                    float gln = e ? ln.y : ln.x;
                    float gir = gix[(size_t)(0 * NH + j) * NB + b];
                    float giz = gix[(size_t)(1 * NH + j) * NB + b];
                    float gin = gix[(size_t)(2 * NH + j) * NB + b];
                    float hold = hin[j * NB + b];
                    float rr = sigm(gir + ghr + sb[jl]);
                    float zz = sigm(giz + ghz + sb[8 + jl]);
                    float nn = tanh_s(gin + gln + rr * (ghn + sb[16 + jl]));
                    hout[j * NB + b] = (1.0f - zz) * nn + zz * hold;
                }
            }
        }
        epoch++; gbar(epoch);

        // ======== logits + argmax + label feedback (CTA c -> batch c) ========
        {
            float part[NL];
            #pragma unroll
            for (int l = 0; l < NL; l++) part[l] = 0.0f;
            for (int k = t; k < NH; k += 256) {
                float hv = hout[k * NB + c];
                const float4* wr = (const float4*)&g_woutT[k * NL];
                #pragma unroll
                for (int q = 0; q < 8; q++) {
                    float4 w = wr[q];
                    part[4*q+0] = fmaf(hv, w.x, part[4*q+0]);
                    part[4*q+1] = fmaf(hv, w.y, part[4*q+1]);
                    part[4*q+2] = fmaf(hv, w.z, part[4*q+2]);
                    part[4*q+3] = fmaf(hv, w.w, part[4*q+3]);
                }
            }
            #pragma unroll
            for (int l = 0; l < NL; l++) sred[t * 33 + l] = part[l];
            __syncthreads();
            if (t < NL) {
                float sum = sbo[t];
                for (int i = 0; i < 256; i++) sum += sred[i * 33 + t];
                stot[t] = sum;
                out[((size_t)c * NS + s) * NL + t] = sum;
            }
            __syncthreads();
            if (t == 0) {
                float best = stot[0]; int bi = 0;
                #pragma unroll
                for (int l = 1; l < NL; l++)
                    if (stot[l] > best) { best = stot[l]; bi = l; }  // first-max == jnp.argmax
                *spred = bi;
            }
            __syncthreads();
            if (t < NE) lout[t * NB + c] = emb[(*spred) * NE + t];
        }
        epoch++; gbar(epoch);
    }
}

// ---------------- launch ----------------
extern "C" void kernel_launch(void* const* d_in, const int* in_sizes, int n_in,
                              void* d_out, int out_size) {
    (void)in_sizes; (void)n_in; (void)out_size;
    const float* x    = (const float*)d_in[0];
    const float* emb  = (const float*)d_in[1];
    const float* Wih  = (const float*)d_in[2];
    const float* Whh  = (const float*)d_in[3];
    const float* bih  = (const float*)d_in[4];
    const float* bhh  = (const float*)d_in[5];
    const float* Wout = (const float*)d_in[6];
    const float* bout = (const float*)d_in[7];
    float* out = (float*)d_out;

    static int smem_set = 0;
    if (!smem_set) {
        cudaFuncSetAttribute(k_seq, cudaFuncAttributeMaxDynamicSharedMemorySize, SMEM_SEQ);
        smem_set = 1;
    }

    k_transpose<<<dim3(NS, NH / 64), 256>>>(x);
    k_init<<<64, 256>>>(emb, Wout);
    k_gemm_a<<<dim3(G3 / 48, NS), 256>>>(Wih, bih);
    k_seq<<<NCTA, 256, SMEM_SEQ>>>(Whh, Wih, bhh, emb, bout, out);
}